// round 14
// baseline (speedup 1.0000x reference)
#include <cuda_runtime.h>
#include <cuda_bf16.h>

// Problem constants
#define NN    1024
#define II    64
#define RTAIL 960          // N - I
#define TAILK 896          // rows 128..1023
#define TAILP 448          // TAILK/2 (bf16x2 pairs)
#define NWARM 25
#define CB    16           // warm cluster size
#define NCTA  128          // total CTAs (8 clusters of 16)
#define NWORK (NCTA - CB)  // 112 gemm workers
#define JB    60           // tail columns per warm block (16*60 = 960)
#define BROWS 16384
#define TM    128

// ---------------- device scratch (static: no allocations allowed) -------------
__device__ float d_C[1024];              // per-column constant, padded zeros
__device__ float d_P[BROWS * 1024];      // raw A@W product (67MB)

// ---------------- helpers ----------------------------------------------------
static __device__ __forceinline__ float sigd(float idv, float e, float iv, float b) {
    return expf(-b * fabsf(e - idv)) - expf(-b * fabsf(iv - idv));
}
static __device__ __forceinline__ unsigned long long splat2(float x) {
    unsigned long long d;
    asm("mov.b64 %0, {%1, %1};" : "=l"(d) : "f"(x));
    return d;
}
static __device__ __forceinline__ unsigned long long ffma2(unsigned long long a,
                                                           unsigned long long b,
                                                           unsigned long long c) {
    unsigned long long d;
    asm("fma.rn.f32x2 %0, %1, %2, %3;" : "=l"(d) : "l"(a), "l"(b), "l"(c));
    return d;
}
static __device__ __forceinline__ void unpack2(unsigned long long v, float& lo, float& hi) {
    asm("mov.b64 {%0, %1}, %2;" : "=f"(lo), "=f"(hi) : "l"(v));
}
static __device__ __forceinline__ float warp_sum(float v) {
    #pragma unroll
    for (int o = 16; o; o >>= 1) v += __shfl_xor_sync(0xffffffffu, v, o);
    return v;
}
static __device__ __forceinline__ unsigned smem_u32(const void* p) {
    unsigned a;
    asm("{ .reg .u64 t; cvta.to.shared.u64 t, %1; cvt.u32.u64 %0, t; }"
        : "=r"(a) : "l"(p));
    return a;
}
static __device__ __forceinline__ void cluster_sync_hw() {
    asm volatile("barrier.cluster.arrive.aligned;" ::: "memory");
    asm volatile("barrier.cluster.wait.aligned;"   ::: "memory");
}
static __device__ __forceinline__ float dsmem_ld(unsigned local_addr, int rank) {
    unsigned rem;
    asm("mapa.shared::cluster.u32 %0, %1, %2;" : "=r"(rem) : "r"(local_addr), "r"(rank));
    float v;
    asm volatile("ld.shared::cluster.f32 %0, [%1];" : "=f"(v) : "r"(rem));
    return v;
}

// ---------------- warm smem layout (float units) ------------------------------
#define OFF_U   (JB * TAILP)          // 26880: u_s[960]
#define OFF_H   (OFF_U + RTAIL)       // h_s[60] (+pad)
#define OFF_XB  (OFF_H + 64)          // xbuf[2][60]
#define OFF_RED (OFF_XB + 2 * JB)     // red[16]
#define WARM_FLOATS (OFF_RED + 16)
#define K1_SMEM (WARM_FLOATS * 4)     // ~112 KB  (worker needs ~101.5 KB)
#define WT 512

// worker smem layout
#define AS_STRIDE 132

// ---------------- kernel 1: warm cluster + overlapped gemm workers -----------
__global__ void __launch_bounds__(WT, 1) __cluster_dims__(CB, 1, 1)
fused_kernel(const float* __restrict__ inp, const float* __restrict__ ids,
             const float* __restrict__ enh, const float* __restrict__ inh,
             const float* __restrict__ beta, const float* __restrict__ delta) {
    extern __shared__ float sm[];
    const float b  = beta[0];
    const float dn = delta[0] * (1.0f / (float)NN);
    const int tid  = threadIdx.x;
    const int bid  = blockIdx.x;
    const int warp = tid >> 5;
    const int lane = tid & 31;

    if (bid < CB) {
        // ================== WARM ROLE (cluster 0, verbatim R9) ===============
        __nv_bfloat162* w2_s = (__nv_bfloat162*)sm;   // [60][448]
        float* u_s = sm + OFF_U;
        float* h_s = sm + OFF_H;
        float* xb  = sm + OFF_XB;
        float* red = sm + OFF_RED;
        const int j0 = bid * JB;

        for (int idx = tid; idx < JB * TAILP; idx += WT) {
            int c = idx / TAILP, i2 = idx - c * TAILP;
            float idv = ids[II + j0 + c];
            int k0 = 128 + 2 * i2;
            float v0 = sigd(idv, enh[k0], inh[k0], b);
            float v1 = sigd(idv, enh[k0 + 1], inh[k0 + 1], b);
            w2_s[idx] = __floats2bfloat162_rn(v0, v1);
        }
        for (int c = warp; c < JB; c += 16) {
            float idv = ids[II + j0 + c];
            float hv = sigd(idv, enh[lane], inh[lane], b)
                     + sigd(idv, enh[lane + 32], inh[lane + 32], b);
            hv = warp_sum(hv);
            if (lane == 0) h_s[c] = hv * (1.0f / (float)NN);
        }
        for (int i = tid; i < RTAIL; i += WT) u_s[i] = 1.0f / (float)NN;
        if (bid == 0 && tid < 64) d_C[RTAIL + tid] = 0.f;
        __syncthreads();

        const int nc = (warp < 15) ? 4 : 0;
        const int cbse = warp * 4;
        const __nv_bfloat162* wp = &w2_s[cbse * TAILP];

        float inv = 1.0f;
        for (int it = 0; it < NWARM; ++it) {
            const int buf = it & 1;
            float acc[4];
            #pragma unroll
            for (int c = 0; c < 4; ++c) acc[c] = 0.f;
            if (nc) {
                #pragma unroll 2
                for (int q = 0; q < 14; ++q) {
                    const int i2 = lane + 32 * q;
                    float2 u2 = *(const float2*)&u_s[64 + 2 * i2];
                    #pragma unroll
                    for (int c = 0; c < 4; ++c) {
                        float2 w = __bfloat1622float2(wp[c * TAILP + i2]);
                        acc[c] = fmaf(u2.y, w.y, fmaf(u2.x, w.x, acc[c]));
                    }
                }
                #pragma unroll
                for (int c = 0; c < 4; ++c) {
                    float dsum = warp_sum(acc[c]);
                    if (lane == 0) {
                        int cl = cbse + c;
                        float uo = u_s[j0 + cl];
                        float nv = fmaxf(uo * inv + dn * (h_s[cl] + dsum * inv), 0.f);
                        xb[buf * JB + cl] = nv;
                    }
                }
            }
            cluster_sync_hw();

            float p = 0.f;
            const unsigned xb_base = smem_u32(&xb[buf * JB]);
            #pragma unroll
            for (int r = 0; r < 2; ++r) {
                int i = tid + WT * r;
                if (i < RTAIL) {
                    int owner = i / JB;
                    int slot  = i - owner * JB;
                    float v = dsmem_ld(xb_base + slot * 4, owner);
                    u_s[i] = v;
                    p += v;
                }
            }
            p = warp_sum(p);
            if (lane == 0) red[warp] = p;
            __syncthreads();
            float sv = (lane < 16) ? red[lane] : 0.f;
            float s = warp_sum(sv);
            inv = (s > 0.f) ? 1.0f / s : 1.0f;
        }

        if (nc) {
            float acc[4];
            #pragma unroll
            for (int c = 0; c < 4; ++c) acc[c] = 0.f;
            #pragma unroll 2
            for (int q = 0; q < 14; ++q) {
                const int i2 = lane + 32 * q;
                float2 u2 = *(const float2*)&u_s[64 + 2 * i2];
                #pragma unroll
                for (int c = 0; c < 4; ++c) {
                    float2 w = __bfloat1622float2(wp[c * TAILP + i2]);
                    acc[c] = fmaf(u2.y, w.y, fmaf(u2.x, w.x, acc[c]));
                }
            }
            #pragma unroll
            for (int c = 0; c < 4; ++c) {
                float dsum = warp_sum(acc[c]);
                if (lane == 0) {
                    int cl = cbse + c;
                    d_C[j0 + cl] = u_s[j0 + cl] * inv + dn * dsum * inv;
                }
            }
        }
        cluster_sync_hw();
    } else {
        // ================== GEMM WORKER ROLE (512 thr, 2 chunks) =============
        float* As = sm;                                  // [64][132] A^T
        float* Ws = As + 64 * AS_STRIDE;                 // [2][64][132]

        const int w    = bid - CB;        // 0..111
        const int pair = w & 3;           // chunk pair: chunks 2p, 2p+1
        const int wc   = w >> 2;          // 0..27 row-tile lane
        const int half = tid >> 8;        // 0/1: which chunk this half handles
        const int t    = tid & 255;
        const int tx = t & 15, ty = t >> 4;
        const int chunk = pair * 2 + half;
        const int cbase = chunk * 128;
        float* Wh = Ws + half * 64 * AS_STRIDE;

        // build my half's W chunk once via MUFU
        for (int idx = t; idx < 64 * 128; idx += 256) {
            int k = idx >> 7, j = idx & 127;
            int col = cbase + j;
            float v = 0.f;
            if (col < RTAIL) v = dn * sigd(ids[II + col], enh[k], inh[k], b);
            Wh[k * AS_STRIDE + j] = v;
        }

        float cv_dummy;
        (void)cv_dummy;
        for (int rt = wc; rt < BROWS / TM; rt += (NWORK >> 2)) {
            const int b0 = rt * TM;
            __syncthreads();   // protect As reuse across tiles
            for (int idx = tid; idx < TM * 64; idx += WT) {
                int row = idx >> 6, k = idx & 63;
                As[k * AS_STRIDE + row] = inp[(b0 + row) * 64 + k];
            }
            __syncthreads();

            unsigned long long acc[8][4];
            #pragma unroll
            for (int r = 0; r < 8; ++r)
                #pragma unroll
                for (int c = 0; c < 4; ++c) acc[r][c] = 0ull;

            #pragma unroll 4
            for (int k = 0; k < 64; ++k) {
                float4 a0 = *(const float4*)&As[k * AS_STRIDE + ty * 8];
                float4 a1 = *(const float4*)&As[k * AS_STRIDE + ty * 8 + 4];
                ulonglong2 w01 = *(const ulonglong2*)&Wh[k * AS_STRIDE + tx * 8];
                ulonglong2 w23 = *(const ulonglong2*)&Wh[k * AS_STRIDE + tx * 8 + 4];
                unsigned long long sp[8];
                sp[0] = splat2(a0.x); sp[1] = splat2(a0.y);
                sp[2] = splat2(a0.z); sp[3] = splat2(a0.w);
                sp[4] = splat2(a1.x); sp[5] = splat2(a1.y);
                sp[6] = splat2(a1.z); sp[7] = splat2(a1.w);
                #pragma unroll
                for (int r = 0; r < 8; ++r) {
                    acc[r][0] = ffma2(sp[r], w01.x, acc[r][0]);
                    acc[r][1] = ffma2(sp[r], w01.y, acc[r][1]);
                    acc[r][2] = ffma2(sp[r], w23.x, acc[r][2]);
                    acc[r][3] = ffma2(sp[r], w23.y, acc[r][3]);
                }
            }

            // store raw P tile (row stride 1024)
            #pragma unroll
            for (int r = 0; r < 8; ++r) {
                int row = b0 + ty * 8 + r;
                float4 v0, v1;
                unpack2(acc[r][0], v0.x, v0.y);
                unpack2(acc[r][1], v0.z, v0.w);
                unpack2(acc[r][2], v1.x, v1.y);
                unpack2(acc[r][3], v1.z, v1.w);
                float4* dst = (float4*)&d_P[row * 1024 + cbase + tx * 8];
                dst[0] = v0;
                dst[1] = v1;
            }
        }
    }
}

// ---------------- kernel 2: epilogue (C + relu + rowsum + normalize) ---------
// 256 CTAs x 256 threads, 64 rows per CTA, 8 rows per warp.  (proven in R7)
__global__ void __launch_bounds__(256)
epi_kernel(float* __restrict__ out) {
    const int tid  = threadIdx.x;
    const int warp = tid >> 5;
    const int lane = tid & 31;
    const int r0   = blockIdx.x * 64 + warp * 8;

    float4 cv[8];
    #pragma unroll
    for (int q = 0; q < 8; ++q)
        cv[q] = *(const float4*)&d_C[lane * 4 + 128 * q];

    #pragma unroll
    for (int r = 0; r < 8; ++r) {
        const int row = r0 + r;
        const float* Pr = &d_P[row * 1024];
        float4 keep;
        float s = 0.f;
        #pragma unroll
        for (int q = 0; q < 8; ++q) {
            float4 p = *(const float4*)&Pr[lane * 4 + 128 * q];
            float4 v;
            v.x = fmaxf(p.x + cv[q].x, 0.f);
            v.y = fmaxf(p.y + cv[q].y, 0.f);
            v.z = fmaxf(p.z + cv[q].z, 0.f);
            v.w = fmaxf(p.w + cv[q].w, 0.f);
            s += (v.x + v.y) + (v.z + v.w);
            if (q == 0) keep = v;
        }
        s = warp_sum(s);
        float inv = (s > 0.f) ? 1.0f / s : 1.0f;
        if (lane < 16) {
            float4 o;
            o.x = keep.x * inv; o.y = keep.y * inv;
            o.z = keep.z * inv; o.w = keep.w * inv;
            *(float4*)&out[row * 64 + lane * 4] = o;
        }
    }
}

// ---------------- launch ------------------------------------------------------
extern "C" void kernel_launch(void* const* d_in, const int* in_sizes, int n_in,
                              void* d_out, int out_size) {
    const float* inputs = (const float*)d_in[0];
    const float* ids    = (const float*)d_in[1];
    const float* enh    = (const float*)d_in[2];
    const float* inh    = (const float*)d_in[3];
    const float* beta   = (const float*)d_in[4];
    const float* delta  = (const float*)d_in[5];

    cudaFuncSetAttribute(fused_kernel,
                         cudaFuncAttributeNonPortableClusterSizeAllowed, 1);
    cudaFuncSetAttribute(fused_kernel,
                         cudaFuncAttributeMaxDynamicSharedMemorySize, K1_SMEM);

    fused_kernel<<<NCTA, WT, K1_SMEM>>>(inputs, ids, enh, inh, beta, delta);
    epi_kernel<<<BROWS / 64, 256>>>((float*)d_out);
}

// round 15
// speedup vs baseline: 1.2699x; 1.2699x over previous
#include <cuda_runtime.h>
#include <cuda_bf16.h>

// Problem constants
#define NN    1024
#define II    64
#define RTAIL 960
#define TAILK 896
#define NWARM 25
#define BROWS 16384

// ---------------- device scratch ----------------------------------------------
__device__ float d_W64[64 * 1024];
__device__ float d_C[1024];
__device__ float d_rowpart[8 * BROWS];

// ---------------- helpers ----------------------------------------------------
static __device__ __forceinline__ float sigd(float idv, float e, float iv, float b) {
    return expf(-b * fabsf(e - idv)) - expf(-b * fabsf(iv - idv));
}
static __device__ __forceinline__ unsigned long long splat2(float x) {
    unsigned long long d;
    asm("mov.b64 %0, {%1, %1};" : "=l"(d) : "f"(x));
    return d;
}
static __device__ __forceinline__ unsigned long long ffma2(unsigned long long a,
                                                           unsigned long long b,
                                                           unsigned long long c) {
    unsigned long long d;
    asm("fma.rn.f32x2 %0, %1, %2, %3;" : "=l"(d) : "l"(a), "l"(b), "l"(c));
    return d;
}
static __device__ __forceinline__ void unpack2(unsigned long long v, float& lo, float& hi) {
    asm("mov.b64 {%0, %1}, %2;" : "=f"(lo), "=f"(hi) : "l"(v));
}
static __device__ __forceinline__ float warp_sum(float v) {
    #pragma unroll
    for (int o = 16; o; o >>= 1) v += __shfl_xor_sync(0xffffffffu, v, o);
    return v;
}
static __device__ __forceinline__ float wiscan_f(float v) {
    int lane = threadIdx.x & 31;
    #pragma unroll
    for (int o = 1; o < 32; o <<= 1) {
        float t = __shfl_up_sync(0xffffffffu, v, o);
        if (lane >= o) v += t;
    }
    return v;
}
static __device__ __forceinline__ int wiscan_i(int v) {
    int lane = threadIdx.x & 31;
    #pragma unroll
    for (int o = 1; o < 32; o <<= 1) {
        int t = __shfl_up_sync(0xffffffffu, v, o);
        if (lane >= o) v += t;
    }
    return v;
}

// ---------------- warm smem layout (4-byte slots) ------------------------------
#define O_SRTV_E 0
#define O_SRTV_I 896
#define O_SRTI_E 1792
#define O_SRTI_I 2688
#define O_EP_E   3584
#define O_EP_I   4480
#define O_EM_E   5376
#define O_EM_I   6272
#define O_S1     7168
#define O_S2     8065
#define O_S3     8962
#define O_S4     9859
#define O_TV     10756
#define O_FE     11716
#define O_GE     12676
#define O_PE     13636
#define O_PI     14596
#define O_HC     15556
#define O_UU     16516
#define O_STARTE 17476
#define O_STARTI 18501
#define O_OFF    19526
#define O_HS     20550
#define O_HSVE   20810
#define O_HSVI   20874
#define O_WTOT   20938
#define O_WOFF   21066
#define O_RED    21194
#define O_SINV   21226
#define WARM_FLOATS 21232
#define WARM_SMEM (WARM_FLOATS * 4)

// ---------------- kernel 1: scan-based warm (block 0) + W64 fill (1..147) -----
__global__ void __launch_bounds__(1024, 1)
warm_kernel(const float* __restrict__ ids, const float* __restrict__ enh,
            const float* __restrict__ inh, const float* __restrict__ beta,
            const float* __restrict__ delta) {
    const float bb = beta[0];
    const float dn = delta[0] * (1.0f / (float)NN);
    const int tid  = threadIdx.x;
    const int bid  = blockIdx.x;

    if (bid > 0) {
        // -------- W64 fill: one element per thread -------------------------
        int idx = (bid - 1) * 1024 + tid;
        if (idx < 64 * 1024) {
            int k = idx >> 10, j = idx & 1023;
            float v = 0.f;
            if (j < RTAIL) v = dn * sigd(ids[II + j], enh[k], inh[k], bb);
            d_W64[idx] = v;
        }
        return;
    }

    extern __shared__ float sm[];
    float* srtv_e = sm + O_SRTV_E;  float* srtv_i = sm + O_SRTV_I;
    int*   srti_e = (int*)(sm + O_SRTI_E);  int* srti_i = (int*)(sm + O_SRTI_I);
    float* ep_e = sm + O_EP_E;  float* ep_i = sm + O_EP_I;
    float* em_e = sm + O_EM_E;  float* em_i = sm + O_EM_I;
    float* S1 = sm + O_S1;  float* S2 = sm + O_S2;
    float* S3 = sm + O_S3;  float* S4 = sm + O_S4;
    float* tv = sm + O_TV;  float* fe = sm + O_FE;  float* ge = sm + O_GE;
    int*   pe = (int*)(sm + O_PE);  int* pi = (int*)(sm + O_PI);
    float* hc = sm + O_HC;  float* uu = sm + O_UU;
    int*   start_e = (int*)(sm + O_STARTE);
    int*   start_i = (int*)(sm + O_STARTI);
    int*   off = (int*)(sm + O_OFF);
    float* hs = sm + O_HS;                 // 4 blocks of 65
    float* hsv_e = sm + O_HSVE;  float* hsv_i = sm + O_HSVI;
    float* wtot = sm + O_WTOT;   float* woff = sm + O_WOFF;
    float* red  = sm + O_RED;

    const int lane = tid & 31;
    const int warpid = tid >> 5;

    // ---- targets: t, fe, ge ------------------------------------------------
    if (tid < RTAIL) {
        float t = ids[II + tid];
        tv[tid] = t;
        fe[tid] = expf(-bb * t);
        ge[tid] = expf(bb * t);
    }

    // ---- bucket sort both tail source arrays -------------------------------
    for (int a = 0; a < 2; ++a) {
        const float* src = (a == 0) ? enh : inh;
        int* startA = (a == 0) ? start_e : start_i;
        float* srtvA = (a == 0) ? srtv_e : srtv_i;
        int*   srtiA = (a == 0) ? srti_e : srti_i;
        float* epA = (a == 0) ? ep_e : ep_i;
        float* emA = (a == 0) ? em_e : em_i;

        startA[tid] = 0;
        off[tid] = 0;
        if (tid == 0) startA[1024] = 0;
        __syncthreads();

        float x = 0.f; int bkt = 0;
        if (tid < TAILK) {
            x = src[128 + tid];
            bkt = min(1023, (int)(x * 1024.0f));
            atomicAdd(&startA[bkt], 1);
        }
        __syncthreads();

        int c = startA[tid];
        int isc = wiscan_i(c);
        int* itmp1 = (int*)red;          // 32
        int* itmp2 = (int*)woff;         // 32
        if (lane == 31) itmp1[warpid] = isc;
        __syncthreads();
        if (warpid == 0) itmp2[lane] = wiscan_i(itmp1[lane]);
        __syncthreads();
        int exc = isc - c + (warpid ? itmp2[warpid - 1] : 0);
        startA[tid] = exc;
        if (tid == 1023) startA[1024] = exc + c;
        __syncthreads();

        if (tid < TAILK) {
            int pos = startA[bkt] + atomicAdd(&off[bkt], 1);
            srtvA[pos] = x;
            srtiA[pos] = 64 + tid;
            epA[pos] = expf(bb * x);
            emA[pos] = expf(-bb * x);
        }
        __syncthreads();
    }

    // ---- target cut positions ----------------------------------------------
    if (tid < RTAIL) {
        float t = tv[tid];
        int bkt = min(1023, (int)(t * 1024.0f));
        int p = start_e[bkt];
        int e = start_e[bkt + 1];
        for (int r = p; r < e; ++r) p += (srtv_e[r] <= t) ? 1 : 0;
        pe[tid] = p;
        int q = start_i[bkt];
        int e2 = start_i[bkt + 1];
        for (int r = start_i[bkt]; r < e2; ++r) q += (srtv_i[r] <= t) ? 1 : 0;
        pi[tid] = q;
    }

    // ---- head constants via 64-element prefix trick ------------------------
    float* hxe = wtot;        // 64 scratch
    float* hxi = woff;        // 64 scratch
    if (tid < 64) hxe[tid] = enh[tid];
    else if (tid < 128) hxi[tid - 64] = inh[tid - 64];
    __syncthreads();
    if (tid < 64) {
        float x = hxe[tid]; int r = 0;
        for (int m = 0; m < 64; ++m) {
            float y = hxe[m];
            r += (y < x || (y == x && m < tid)) ? 1 : 0;
        }
        hsv_e[r] = x;
    } else if (tid < 128) {
        int t0 = tid - 64;
        float x = hxi[t0]; int r = 0;
        for (int m = 0; m < 64; ++m) {
            float y = hxi[m];
            r += (y < x || (y == x && m < t0)) ? 1 : 0;
        }
        hsv_i[r] = x;
    }
    __syncthreads();
    if (tid < 64) {
        hs[0 * 65 + tid + 1] = expf(bb * hsv_e[tid]);
        hs[1 * 65 + tid + 1] = expf(-bb * hsv_e[tid]);
    } else if (tid < 128) {
        int r = tid - 64;
        hs[2 * 65 + r + 1] = expf(bb * hsv_i[r]);
        hs[3 * 65 + r + 1] = expf(-bb * hsv_i[r]);
    }
    __syncthreads();
    if (tid == 0) {
        for (int a = 0; a < 4; ++a) {
            hs[a * 65] = 0.f;
            for (int r = 1; r <= 64; ++r) hs[a * 65 + r] += hs[a * 65 + r - 1];
        }
    }
    __syncthreads();
    if (tid < RTAIL) {
        float t = tv[tid];
        int p = 0, q = 0;
        for (int m = 0; m < 64; ++m) {
            p += (hxe[m] <= t) ? 1 : 0;
            q += (hxi[m] <= t) ? 1 : 0;
        }
        float he = fe[tid] * hs[0 * 65 + p] + ge[tid] * (hs[1 * 65 + 64] - hs[1 * 65 + p]);
        float hi = fe[tid] * hs[2 * 65 + q] + ge[tid] * (hs[3 * 65 + 64] - hs[3 * 65 + q]);
        hc[tid] = (he - hi) * (1.0f / (float)NN);
    }
    if (tid < RTAIL) uu[tid] = 1.0f / (float)NN;
    if (tid < 64) d_C[RTAIL + tid] = 0.f;
    __syncthreads();

    // ---- 25 warm steps ------------------------------------------------------
    float inv = 1.0f;
    for (int it = 0; it < NWARM; ++it) {
        // A: scaled source weights (read u)
        float w0 = 0.f, w1 = 0.f, w2 = 0.f, w3 = 0.f;
        if (tid < TAILK) {
            float ue = uu[srti_e[tid]];
            w0 = ue * ep_e[tid];  w1 = ue * em_e[tid];
            float ui2 = uu[srti_i[tid]];
            w2 = ui2 * ep_i[tid]; w3 = ui2 * em_i[tid];
        }
        // B: 4 block scans
        float s0 = wiscan_f(w0), s1v = wiscan_f(w1), s2v = wiscan_f(w2), s3v = wiscan_f(w3);
        if (lane == 31) {
            wtot[warpid] = s0; wtot[32 + warpid] = s1v;
            wtot[64 + warpid] = s2v; wtot[96 + warpid] = s3v;
        }
        __syncthreads();
        if (warpid == 0) {
            woff[lane]      = wiscan_f(wtot[lane]);
            woff[32 + lane] = wiscan_f(wtot[32 + lane]);
            woff[64 + lane] = wiscan_f(wtot[64 + lane]);
            woff[96 + lane] = wiscan_f(wtot[96 + lane]);
        }
        __syncthreads();
        float o0 = 0.f, o1 = 0.f, o2 = 0.f, o3 = 0.f;
        if (warpid > 0) {
            o0 = woff[warpid - 1];      o1 = woff[32 + warpid - 1];
            o2 = woff[64 + warpid - 1]; o3 = woff[96 + warpid - 1];
        }
        if (tid < TAILK) {
            S1[tid + 1] = o0 + s0;  S2[tid + 1] = o1 + s1v;
            S3[tid + 1] = o2 + s2v; S4[tid + 1] = o3 + s3v;
        }
        if (tid == 0) { S1[0] = 0.f; S2[0] = 0.f; S3[0] = 0.f; S4[0] = 0.f; }
        __syncthreads();

        // C: target evaluation + in-place u update
        float nv = 0.f;
        if (tid < RTAIL) {
            int p = pe[tid], q = pi[tid];
            float dote = fe[tid] * S1[p] + ge[tid] * (S2[TAILK] - S2[p]);
            float doti = fe[tid] * S3[q] + ge[tid] * (S4[TAILK] - S4[q]);
            float dot = dote - doti;
            nv = fmaxf(uu[tid] * inv + dn * (hc[tid] + dot * inv), 0.f);
            uu[tid] = nv;
        }
        // D: s-reduce -> inv for next step
        float ps = warp_sum(nv);
        if (lane == 0) red[warpid] = ps;
        __syncthreads();
        if (warpid == 0) {
            float sv = red[lane];
            float s = warp_sum(sv);
            if (lane == 0) sm[O_SINV] = (s > 0.f) ? 1.0f / s : 1.0f;
        }
        __syncthreads();
        inv = sm[O_SINV];
    }

    // ---- final C: scans of final u, C_j = u*inv + dn*dot*inv ----------------
    {
        float w0 = 0.f, w1 = 0.f, w2 = 0.f, w3 = 0.f;
        if (tid < TAILK) {
            float ue = uu[srti_e[tid]];
            w0 = ue * ep_e[tid];  w1 = ue * em_e[tid];
            float ui2 = uu[srti_i[tid]];
            w2 = ui2 * ep_i[tid]; w3 = ui2 * em_i[tid];
        }
        float s0 = wiscan_f(w0), s1v = wiscan_f(w1), s2v = wiscan_f(w2), s3v = wiscan_f(w3);
        if (lane == 31) {
            wtot[warpid] = s0; wtot[32 + warpid] = s1v;
            wtot[64 + warpid] = s2v; wtot[96 + warpid] = s3v;
        }
        __syncthreads();
        if (warpid == 0) {
            woff[lane]      = wiscan_f(wtot[lane]);
            woff[32 + lane] = wiscan_f(wtot[32 + lane]);
            woff[64 + lane] = wiscan_f(wtot[64 + lane]);
            woff[96 + lane] = wiscan_f(wtot[96 + lane]);
        }
        __syncthreads();
        float o0 = 0.f, o1 = 0.f, o2 = 0.f, o3 = 0.f;
        if (warpid > 0) {
            o0 = woff[warpid - 1];      o1 = woff[32 + warpid - 1];
            o2 = woff[64 + warpid - 1]; o3 = woff[96 + warpid - 1];
        }
        if (tid < TAILK) {
            S1[tid + 1] = o0 + s0;  S2[tid + 1] = o1 + s1v;
            S3[tid + 1] = o2 + s2v; S4[tid + 1] = o3 + s3v;
        }
        if (tid == 0) { S1[0] = 0.f; S2[0] = 0.f; S3[0] = 0.f; S4[0] = 0.f; }
        __syncthreads();

        if (tid < RTAIL) {
            int p = pe[tid], q = pi[tid];
            float dote = fe[tid] * S1[p] + ge[tid] * (S2[TAILK] - S2[p]);
            float doti = fe[tid] * S3[q] + ge[tid] * (S4[TAILK] - S4[q]);
            float dot = dote - doti;
            d_C[tid] = uu[tid] * inv + dn * dot * inv;
        }
    }
}

// ---------------- kernel 2: GEMM, grid = (row tiles, 8 col chunks) -----------
#define TM 128
#define AS_STRIDE 132
#define SMEM_GEMM ((64 * AS_STRIDE + 64 * AS_STRIDE + 256) * 4)

__global__ void __launch_bounds__(256)
gemm_kernel(const float* __restrict__ inp, float* __restrict__ out) {
    extern __shared__ float sm[];
    float* As = sm;
    float* Ws = As + 64 * AS_STRIDE;
    float* rs = Ws + 64 * AS_STRIDE;

    const int tid  = threadIdx.x;
    const int lane = tid & 31;
    const int wid  = tid >> 5;
    const int tx = (lane & 7) | ((wid & 1) << 3);
    const int ty = (lane >> 3) | ((wid >> 1) << 2);
    const int b0 = blockIdx.x * TM;
    const int chunk = blockIdx.y;
    const int cbase = chunk * 128;

    for (int idx = tid; idx < TM * 64; idx += 256) {
        int row = idx >> 6, k = idx & 63;
        As[k * AS_STRIDE + row] = inp[(b0 + row) * 64 + k];
    }
    for (int idx = tid; idx < 64 * 128; idx += 256) {
        int k = idx >> 7, j = idx & 127;
        Ws[k * AS_STRIDE + j] = d_W64[k * 1024 + cbase + j];
    }
    __syncthreads();

    unsigned long long acc[8][4];
    #pragma unroll
    for (int r = 0; r < 8; ++r)
        #pragma unroll
        for (int c = 0; c < 4; ++c) acc[r][c] = 0ull;

    #pragma unroll 4
    for (int k = 0; k < 64; ++k) {
        float4 a0 = *(const float4*)&As[k * AS_STRIDE + ty * 8];
        float4 a1 = *(const float4*)&As[k * AS_STRIDE + ty * 8 + 4];
        ulonglong2 w01 = *(const ulonglong2*)&Ws[k * AS_STRIDE + tx * 8];
        ulonglong2 w23 = *(const ulonglong2*)&Ws[k * AS_STRIDE + tx * 8 + 4];
        unsigned long long sp[8];
        sp[0] = splat2(a0.x); sp[1] = splat2(a0.y);
        sp[2] = splat2(a0.z); sp[3] = splat2(a0.w);
        sp[4] = splat2(a1.x); sp[5] = splat2(a1.y);
        sp[6] = splat2(a1.z); sp[7] = splat2(a1.w);
        #pragma unroll
        for (int r = 0; r < 8; ++r) {
            acc[r][0] = ffma2(sp[r], w01.x, acc[r][0]);
            acc[r][1] = ffma2(sp[r], w01.y, acc[r][1]);
            acc[r][2] = ffma2(sp[r], w23.x, acc[r][2]);
            acc[r][3] = ffma2(sp[r], w23.y, acc[r][3]);
        }
    }

    float cv[8];
    #pragma unroll
    for (int cc = 0; cc < 8; ++cc) cv[cc] = d_C[cbase + tx * 8 + cc];
    const bool store0 = (chunk == 0) && (tx < 8);

    float s_part[8];
    #pragma unroll
    for (int r = 0; r < 8; ++r) {
        int row = ty * 8 + r;
        float sp_r = 0.f;
        #pragma unroll
        for (int cp = 0; cp < 4; ++cp) {
            float lo, hi;
            unpack2(acc[r][cp], lo, hi);
            float v0 = fmaxf(cv[cp * 2] + lo, 0.f);
            float v1 = fmaxf(cv[cp * 2 + 1] + hi, 0.f);
            sp_r += v0 + v1;
            if (store0) {
                out[(b0 + row) * 64 + tx * 8 + cp * 2]     = v0;
                out[(b0 + row) * 64 + tx * 8 + cp * 2 + 1] = v1;
            }
        }
        s_part[r] = sp_r;
    }
    #pragma unroll
    for (int r = 0; r < 8; ++r) {
        #pragma unroll
        for (int m = 1; m < 8; m <<= 1)
            s_part[r] += __shfl_xor_sync(0xffffffffu, s_part[r], m);
    }
    if ((lane & 7) == 0) {
        #pragma unroll
        for (int r = 0; r < 8; ++r)
            rs[(ty * 8 + r) * 2 + (wid & 1)] = s_part[r];
    }
    __syncthreads();
    if (tid < TM)
        d_rowpart[chunk * BROWS + b0 + tid] = rs[tid * 2] + rs[tid * 2 + 1];
}

// ---------------- kernel 3: normalize rows (in-place on out) -----------------
__global__ void __launch_bounds__(256)
scale_kernel(float* __restrict__ out) {
    __shared__ float inv_s[256];
    const int tid = threadIdx.x;
    const int base = blockIdx.x * 256;

    float s = 0.f;
    #pragma unroll
    for (int c = 0; c < 8; ++c) s += d_rowpart[c * BROWS + base + tid];
    inv_s[tid] = (s > 0.f) ? 1.0f / s : 1.0f;
    __syncthreads();

    for (int idx = tid; idx < 256 * 64; idx += 256) {
        int r = idx >> 6;
        out[base * 64 + idx] *= inv_s[r];
    }
}

// ---------------- launch ------------------------------------------------------
extern "C" void kernel_launch(void* const* d_in, const int* in_sizes, int n_in,
                              void* d_out, int out_size) {
    const float* inputs = (const float*)d_in[0];
    const float* ids    = (const float*)d_in[1];
    const float* enh    = (const float*)d_in[2];
    const float* inh    = (const float*)d_in[3];
    const float* beta   = (const float*)d_in[4];
    const float* delta  = (const float*)d_in[5];

    cudaFuncSetAttribute(warm_kernel,
                         cudaFuncAttributeMaxDynamicSharedMemorySize, WARM_SMEM);
    cudaFuncSetAttribute(gemm_kernel,
                         cudaFuncAttributeMaxDynamicSharedMemorySize, SMEM_GEMM);

    warm_kernel<<<148, 1024, WARM_SMEM>>>(ids, enh, inh, beta, delta);

    dim3 grid(BROWS / TM, 8);
    gemm_kernel<<<grid, 256, SMEM_GEMM>>>(inputs, (float*)d_out);

    scale_kernel<<<BROWS / 256, 256>>>((float*)d_out);
}